// round 8
// baseline (speedup 1.0000x reference)
#include <cuda_runtime.h>
#include <cstdint>

// FuzzyNeuron via mma.sync tf32 tensor cores (3xTF32 split).
// S[m, n<64]   = logw2[m, rule n]   (f*log2e added in epilogue)
// S[m, 64+n]   = z[m, rule n]       (bias added in epilogue)
// A[m, 0:16]=x, A[m,16:32]=x^2 (tf32 hi + lo residual). K=32.
// B[k, n]: k<16 -> {2*c*mu*log2e | rho}, k>=16 -> {-c*log2e | 0}.
// 3 products per (ntile,kstep): Ahi*Bhi + Alo*Bhi + Ahi*Blo.
// Per-chunk epilogue (rule ntile j paired with z ntile j+8) frees C regs.

typedef unsigned int u32;

#define LOG2E 1.4426950408889634f
#define BLOCK 128          // 4 warps; each warp does 32 rows -> 128 rows/CTA
#define BPAD 132           // float2 row stride (pad kills k-stride bank conflicts)

__device__ float2 gB[32 * 128];   // [k][n] {tf32 hi, tf32 lo}
__device__ float2 gFB[64];        // {f*log2e, bias}

__device__ __forceinline__ u32 tf32_bits(float v) {
    u32 r; asm("cvt.rna.tf32.f32 %0, %1;" : "=r"(r) : "f"(v)); return r;
}
__device__ __forceinline__ float tf32_rna(float v) {
    return __uint_as_float(tf32_bits(v));
}
__device__ __forceinline__ float exp2_fast(float v) {
    float r; asm("ex2.approx.ftz.f32 %0, %1;" : "=f"(r) : "f"(v)); return r;
}
__device__ __forceinline__ void mma8(float* c, const u32* a, u32 b0, u32 b1) {
    asm volatile(
        "mma.sync.aligned.m16n8k8.row.col.f32.tf32.tf32.f32 "
        "{%0,%1,%2,%3}, {%4,%5,%6,%7}, {%8,%9}, {%0,%1,%2,%3};"
        : "+f"(c[0]), "+f"(c[1]), "+f"(c[2]), "+f"(c[3])
        : "r"(a[0]), "r"(a[1]), "r"(a[2]), "r"(a[3]), "r"(b0), "r"(b1));
}

// ---------------- prep: B matrix (tf32 hi/lo) + per-rule constants ----------------
__global__ void prep_kernel(const float* __restrict__ mu,
                            const float* __restrict__ sigma,
                            const float* __restrict__ rho) {
    int tid = threadIdx.x;
    for (int i = tid; i < 32 * 128; i += 128) {
        int k = i >> 7, n = i & 127;
        float v;
        if (n < 64) {                    // logw columns, rule r = n
            if (k < 16) {
                float m = mu[n * 16 + k], s = sigma[n * 16 + k];
                float c = 1.0f / (2.0f * s * s);
                v = 2.0f * c * m * LOG2E;            // multiplies x
            } else {
                float s = sigma[n * 16 + (k - 16)];
                v = -(1.0f / (2.0f * s * s)) * LOG2E; // multiplies x^2
            }
        } else {                          // z columns, rule r = n-64
            v = (k < 16) ? rho[(n - 64) * 17 + k] : 0.0f;
        }
        float hi = tf32_rna(v);
        float lo = tf32_rna(v - hi);
        gB[i] = make_float2(hi, lo);
    }
    for (int r = tid; r < 64; r += 128) {
        float f = 0.0f;
        for (int a = 0; a < 16; a++) {
            float m = mu[r * 16 + a], s = sigma[r * 16 + a];
            f -= (m * m) / (2.0f * s * s);
        }
        gFB[r] = make_float2(f * LOG2E, rho[r * 17 + 16]);
    }
}

// ---------------- main kernel ----------------
__global__ void __launch_bounds__(BLOCK, 4)
fuzzy_mma_kernel(const float* __restrict__ x, float* __restrict__ out) {
    __shared__ float2 sB[32 * BPAD];                 // 33 KB, padded
    __shared__ __align__(16) float2 sFB[64];

    const int tid = threadIdx.x;
    const int w = tid >> 5, lane = tid & 31;
    const int g = lane >> 2, tig = lane & 3;

    for (int i = tid; i < 32 * 128; i += BLOCK) {
        int k = i >> 7, n = i & 127;
        sB[k * BPAD + n] = gB[i];
    }
    if (tid < 64) sFB[tid] = gFB[tid];
    __syncthreads();

    const int rowBase = blockIdx.x * BLOCK + w * 32;

    // ---- A fragments: rows {g, g+8} of 2 m-tiles; cols tig+4e ----
    // slot layout per mma: a0=(row g,col c), a1=(g+8,c), a2=(g,c+4), a3=(g+8,c+4)
    u32 ah[2][4][4], al[2][4][4];
#pragma unroll
    for (int mt = 0; mt < 2; mt++)
#pragma unroll
        for (int rh = 0; rh < 2; rh++) {
            const float* xr = x + (size_t)(rowBase + mt * 16 + rh * 8 + g) * 16 + tig;
#pragma unroll
            for (int e = 0; e < 4; e++) {
                float v = xr[4 * e];
                u32 vh = tf32_bits(v);
                u32 vl = tf32_bits(v - __uint_as_float(vh));
                float v2 = v * v;
                u32 v2h = tf32_bits(v2);
                u32 v2l = tf32_bits(v2 - __uint_as_float(v2h));
                int ks = e >> 1;          // kstep within x-half
                int slot = (e & 1) * 2 + rh;
                ah[mt][ks][slot] = vh;      al[mt][ks][slot] = vl;
                ah[mt][2 + ks][slot] = v2h; al[mt][2 + ks][slot] = v2l;
            }
        }

    float num[2][2] = {{0.f, 0.f}, {0.f, 0.f}};
    float den[2][2] = {{0.f, 0.f}, {0.f, 0.f}};

    // ---- rule chunks: logw ntile j (cols 8j..8j+7) + z ntile j+8 ----
    for (int j = 0; j < 8; j++) {
        float cl[2][4] = {{0.f, 0.f, 0.f, 0.f}, {0.f, 0.f, 0.f, 0.f}};
        float cz[2][4] = {{0.f, 0.f, 0.f, 0.f}, {0.f, 0.f, 0.f, 0.f}};
#pragma unroll
        for (int ks = 0; ks < 4; ks++) {
            const float2* b0p = &sB[(ks * 8 + tig) * BPAD + j * 8 + g];
            const float2* b1p = &sB[(ks * 8 + tig + 4) * BPAD + j * 8 + g];
            float2 Bl0 = b0p[0],  Bl1 = b1p[0];     // logw cols
            float2 Bz0 = b0p[64], Bz1 = b1p[64];    // z cols (+64)
            u32 bl0h = __float_as_uint(Bl0.x), bl1h = __float_as_uint(Bl1.x);
            u32 bl0l = __float_as_uint(Bl0.y), bl1l = __float_as_uint(Bl1.y);
            u32 bz0h = __float_as_uint(Bz0.x), bz1h = __float_as_uint(Bz1.x);
            u32 bz0l = __float_as_uint(Bz0.y), bz1l = __float_as_uint(Bz1.y);
#pragma unroll
            for (int mt = 0; mt < 2; mt++) {
                mma8(cl[mt], ah[mt][ks], bl0h, bl1h);   // Ahi * Bhi
                mma8(cl[mt], al[mt][ks], bl0h, bl1h);   // Alo * Bhi
                mma8(cl[mt], ah[mt][ks], bl0l, bl1l);   // Ahi * Blo
                mma8(cz[mt], ah[mt][ks], bz0h, bz1h);
                mma8(cz[mt], al[mt][ks], bz0h, bz1h);
                mma8(cz[mt], ah[mt][ks], bz0l, bz1l);
            }
        }
        // epilogue for rules c0 = 8j+2tig, c1 = c0+1 (same thread holds z pair)
        float4 q = *reinterpret_cast<const float4*>(&sFB[8 * j + 2 * tig]);  // {f0,b0,f1,b1}
#pragma unroll
        for (int mt = 0; mt < 2; mt++) {
            float w00 = exp2_fast(cl[mt][0] + q.x);
            float w01 = exp2_fast(cl[mt][1] + q.z);
            float w10 = exp2_fast(cl[mt][2] + q.x);
            float w11 = exp2_fast(cl[mt][3] + q.z);
            num[mt][0] = fmaf(cz[mt][0] + q.y, w00, num[mt][0]);
            num[mt][0] = fmaf(cz[mt][1] + q.w, w01, num[mt][0]);
            num[mt][1] = fmaf(cz[mt][2] + q.y, w10, num[mt][1]);
            num[mt][1] = fmaf(cz[mt][3] + q.w, w11, num[mt][1]);
            den[mt][0] += w00 + w01;
            den[mt][1] += w10 + w11;
        }
    }

    // ---- reduce across the 4 tig lanes, write 4 rows per tig==0 lane ----
#pragma unroll
    for (int mt = 0; mt < 2; mt++)
#pragma unroll
        for (int rh = 0; rh < 2; rh++) {
            float n = num[mt][rh], d = den[mt][rh];
            n += __shfl_xor_sync(0xffffffffu, n, 1);
            d += __shfl_xor_sync(0xffffffffu, d, 1);
            n += __shfl_xor_sync(0xffffffffu, n, 2);
            d += __shfl_xor_sync(0xffffffffu, d, 2);
            if (tig == 0)
                out[rowBase + mt * 16 + rh * 8 + g] = n / (d + 1e-13f);
        }
}

extern "C" void kernel_launch(void* const* d_in, const int* in_sizes, int n_in,
                              void* d_out, int out_size) {
    const float* x = (const float*)d_in[0];      // [N, 16]
    const float* mu = (const float*)d_in[1];     // [64, 16]
    const float* sigma = (const float*)d_in[2];  // [64, 16]
    const float* rho = (const float*)d_in[3];    // [64, 17]
    float* out = (float*)d_out;                  // [N]

    const int n_rows = in_sizes[0] / 16;         // 131072
    prep_kernel<<<1, 128>>>(mu, sigma, rho);
    fuzzy_mma_kernel<<<n_rows / BLOCK, BLOCK>>>(x, out);
}

// round 9
// speedup vs baseline: 1.2452x; 1.2452x over previous
#include <cuda_runtime.h>
#include <cstdint>

// FuzzyNeuron via mma.sync tf32 tensor cores — fused single kernel.
// S_logw[m, r] = logw2 = x.b~ + x^2.q~   (3xTF32: AhiBhi + AloBhi + AhiBlo, K=32)
// S_z[m, r]    = x.rho                    (1x tf32 hi product, K=16)
// Epilogue: w = ex2(logw2 + f~), out = sum(z+bias)*w / (sum w + 1e-13).
// Each CTA builds B in smem from mu/sigma/rho (no prep kernel, no globals).

typedef unsigned int u32;

#define LOG2E 1.4426950408889634f
#define BLOCK 128      // 4 warps x 32 rows = 128 rows/CTA
#define PL 68          // sBl float2 row stride: 2*68 % 32 == 8 -> conflict-free LDS.64
#define PZ 72          // sBz float  row stride:   72 % 32 == 8 -> conflict-free LDS.32

__device__ __forceinline__ u32 tf32_bits(float v) {
    u32 r; asm("cvt.rna.tf32.f32 %0, %1;" : "=r"(r) : "f"(v)); return r;
}
__device__ __forceinline__ float exp2_fast(float v) {
    float r; asm("ex2.approx.ftz.f32 %0, %1;" : "=f"(r) : "f"(v)); return r;
}
__device__ __forceinline__ void mma8(float* c, const u32* a, u32 b0, u32 b1) {
    asm volatile(
        "mma.sync.aligned.m16n8k8.row.col.f32.tf32.tf32.f32 "
        "{%0,%1,%2,%3}, {%4,%5,%6,%7}, {%8,%9}, {%0,%1,%2,%3};"
        : "+f"(c[0]), "+f"(c[1]), "+f"(c[2]), "+f"(c[3])
        : "r"(a[0]), "r"(a[1]), "r"(a[2]), "r"(a[3]), "r"(b0), "r"(b1));
}

__global__ void __launch_bounds__(BLOCK, 4)
fuzzy_mma_kernel(const float* __restrict__ x,
                 const float* __restrict__ mu,
                 const float* __restrict__ sigma,
                 const float* __restrict__ rho,
                 float* __restrict__ out) {
    __shared__ float2 sBl[32 * PL];               // logw B {tf32 hi, lo}, 17.4 KB
    __shared__ float  sBz[16 * PZ];               // z B (tf32 hi only), 4.6 KB
    __shared__ __align__(16) float2 sFB[64];      // {f*log2e, bias}

    const int tid = threadIdx.x;
    const int w = tid >> 5, lane = tid & 31;
    const int g = lane >> 2, tig = lane & 3;

    // ---- build B in smem: i -> (kk = i&15, n = i>>4) so mu/sigma reads coalesce ----
    for (int i = tid; i < 1024; i += BLOCK) {
        int kk = i & 15, n = i >> 4;
        float m = mu[n * 16 + kk], s = sigma[n * 16 + kk];
        float c = 1.0f / (2.0f * s * s);
        float bt = 2.0f * c * m * LOG2E;          // multiplies x
        float qt = -c * LOG2E;                    // multiplies x^2
        u32 bh = tf32_bits(bt);
        u32 qh = tf32_bits(qt);
        sBl[kk * PL + n] = make_float2(__uint_as_float(bh),
                                       bt - __uint_as_float(bh));
        sBl[(kk + 16) * PL + n] = make_float2(__uint_as_float(qh),
                                              qt - __uint_as_float(qh));
        // lo residuals are small; tf32_rna of them == themselves in effect for mma
        sBz[kk * PZ + n] = __uint_as_float(tf32_bits(rho[n * 17 + kk]));
    }
    if (tid < 64) {
        float f = 0.0f;
        for (int a = 0; a < 16; a++) {
            float m = mu[tid * 16 + a], s = sigma[tid * 16 + a];
            f -= (m * m) / (2.0f * s * s);
        }
        sFB[tid] = make_float2(f * LOG2E, rho[tid * 17 + 16]);
    }
    __syncthreads();

    const int rowBase = blockIdx.x * BLOCK + w * 32;

    // ---- A fragments: rows {g, g+8} of 2 m-tiles; cols tig+4e ----
    u32 ah[2][4][4], al[2][4][4];
#pragma unroll
    for (int mt = 0; mt < 2; mt++)
#pragma unroll
        for (int rh = 0; rh < 2; rh++) {
            const float* xr = x + (size_t)(rowBase + mt * 16 + rh * 8 + g) * 16 + tig;
#pragma unroll
            for (int e = 0; e < 4; e++) {
                float v = xr[4 * e];
                u32 vh = tf32_bits(v);
                u32 vl = tf32_bits(v - __uint_as_float(vh));
                float v2 = v * v;
                u32 v2h = tf32_bits(v2);
                u32 v2l = tf32_bits(v2 - __uint_as_float(v2h));
                int ks = e >> 1;
                int slot = (e & 1) * 2 + rh;
                ah[mt][ks][slot] = vh;      al[mt][ks][slot] = vl;
                ah[mt][2 + ks][slot] = v2h; al[mt][2 + ks][slot] = v2l;
            }
        }

    float num[2][2] = {{0.f, 0.f}, {0.f, 0.f}};
    float den[2][2] = {{0.f, 0.f}, {0.f, 0.f}};

    // ---- 8 rule chunks of 8 rules (cols 8j..8j+7) ----
    for (int j = 0; j < 8; j++) {
        float cl[2][4] = {{0.f, 0.f, 0.f, 0.f}, {0.f, 0.f, 0.f, 0.f}};
        float cz[2][4] = {{0.f, 0.f, 0.f, 0.f}, {0.f, 0.f, 0.f, 0.f}};
#pragma unroll
        for (int ks = 0; ks < 4; ks++) {
            float2 Bl0 = sBl[(ks * 8 + tig) * PL + j * 8 + g];
            float2 Bl1 = sBl[(ks * 8 + tig + 4) * PL + j * 8 + g];
            u32 b0h = __float_as_uint(Bl0.x), b1h = __float_as_uint(Bl1.x);
            u32 b0l = __float_as_uint(Bl0.y), b1l = __float_as_uint(Bl1.y);
#pragma unroll
            for (int mt = 0; mt < 2; mt++) {
                mma8(cl[mt], ah[mt][ks], b0h, b1h);   // Ahi*Bhi
                mma8(cl[mt], al[mt][ks], b0h, b1h);   // Alo*Bhi
                mma8(cl[mt], ah[mt][ks], b0l, b1l);   // Ahi*Blo
            }
        }
#pragma unroll
        for (int ks = 0; ks < 2; ks++) {              // z: K=16, hi only
            u32 bz0 = __float_as_uint(sBz[(ks * 8 + tig) * PZ + j * 8 + g]);
            u32 bz1 = __float_as_uint(sBz[(ks * 8 + tig + 4) * PZ + j * 8 + g]);
#pragma unroll
            for (int mt = 0; mt < 2; mt++)
                mma8(cz[mt], ah[mt][ks], bz0, bz1);
        }
        // epilogue for rules 8j+2tig, 8j+2tig+1 (this thread holds both z cols)
        float4 q = *reinterpret_cast<const float4*>(&sFB[8 * j + 2 * tig]); // {f0,b0,f1,b1}
#pragma unroll
        for (int mt = 0; mt < 2; mt++) {
            float w00 = exp2_fast(cl[mt][0] + q.x);
            float w01 = exp2_fast(cl[mt][1] + q.z);
            float w10 = exp2_fast(cl[mt][2] + q.x);
            float w11 = exp2_fast(cl[mt][3] + q.z);
            num[mt][0] = fmaf(cz[mt][0] + q.y, w00, num[mt][0]);
            num[mt][0] = fmaf(cz[mt][1] + q.w, w01, num[mt][0]);
            num[mt][1] = fmaf(cz[mt][2] + q.y, w10, num[mt][1]);
            num[mt][1] = fmaf(cz[mt][3] + q.w, w11, num[mt][1]);
            den[mt][0] += w00 + w01;
            den[mt][1] += w10 + w11;
        }
    }

    // ---- reduce across 4 tig lanes; tig==0 writes 4 rows ----
#pragma unroll
    for (int mt = 0; mt < 2; mt++)
#pragma unroll
        for (int rh = 0; rh < 2; rh++) {
            float n = num[mt][rh], d = den[mt][rh];
            n += __shfl_xor_sync(0xffffffffu, n, 1);
            d += __shfl_xor_sync(0xffffffffu, d, 1);
            n += __shfl_xor_sync(0xffffffffu, n, 2);
            d += __shfl_xor_sync(0xffffffffu, d, 2);
            if (tig == 0)
                out[rowBase + mt * 16 + rh * 8 + g] = n / (d + 1e-13f);
        }
}

extern "C" void kernel_launch(void* const* d_in, const int* in_sizes, int n_in,
                              void* d_out, int out_size) {
    const float* x = (const float*)d_in[0];      // [N, 16]
    const float* mu = (const float*)d_in[1];     // [64, 16]
    const float* sigma = (const float*)d_in[2];  // [64, 16]
    const float* rho = (const float*)d_in[3];    // [64, 17]
    float* out = (float*)d_out;                  // [N]

    const int n_rows = in_sizes[0] / 16;         // 131072
    fuzzy_mma_kernel<<<n_rows / BLOCK, BLOCK>>>(x, mu, sigma, rho, out);
}

// round 10
// speedup vs baseline: 1.3561x; 1.0890x over previous
#include <cuda_runtime.h>
#include <cstdint>

// FuzzyNeuron via mma.sync tf32 (3xTF32 for logw, 1x for z), fused kernel.
// R10: (a) 3-way split logw accumulators -> max MMA chain 12 -> 4 (RAW stall
// was the R9 binder: tensor 23%, issue 32%); (b) persistent CTAs, grid=512
// (one full wave, 2 tiles/CTA) amortizing B-build; (c) fast-div setup.

typedef unsigned int u32;

#define LOG2E 1.4426950408889634f
#define BLOCK 128      // 4 warps x 32 rows = 128 rows/tile
#define PL 68          // sBl float2 row stride: 2*68 % 32 == 8 -> conflict-free
#define PZ 72          // sBz float  row stride:   72 % 32 == 8 -> conflict-free
#define GRID 512
#define TILES 2        // 512 CTAs x 2 tiles x 128 rows = 131072

__device__ __forceinline__ u32 tf32_bits(float v) {
    u32 r; asm("cvt.rna.tf32.f32 %0, %1;" : "=r"(r) : "f"(v)); return r;
}
__device__ __forceinline__ float exp2_fast(float v) {
    float r; asm("ex2.approx.ftz.f32 %0, %1;" : "=f"(r) : "f"(v)); return r;
}
__device__ __forceinline__ void mma8(float* c, const u32* a, u32 b0, u32 b1) {
    asm volatile(
        "mma.sync.aligned.m16n8k8.row.col.f32.tf32.tf32.f32 "
        "{%0,%1,%2,%3}, {%4,%5,%6,%7}, {%8,%9}, {%0,%1,%2,%3};"
        : "+f"(c[0]), "+f"(c[1]), "+f"(c[2]), "+f"(c[3])
        : "r"(a[0]), "r"(a[1]), "r"(a[2]), "r"(a[3]), "r"(b0), "r"(b1));
}

__global__ void __launch_bounds__(BLOCK, 4)
fuzzy_mma_kernel(const float* __restrict__ x,
                 const float* __restrict__ mu,
                 const float* __restrict__ sigma,
                 const float* __restrict__ rho,
                 float* __restrict__ out) {
    __shared__ float2 sBl[32 * PL];               // logw B {tf32 hi, lo}
    __shared__ float  sBz[16 * PZ];               // z B (tf32 hi only)
    __shared__ __align__(16) float2 sFB[64];      // {f*log2e, bias}

    const int tid = threadIdx.x;
    const int w = tid >> 5, lane = tid & 31;
    const int g = lane >> 2, tig = lane & 3;

    // ---- build B in smem (once per CTA, amortized over TILES tiles) ----
    for (int i = tid; i < 1024; i += BLOCK) {
        int kk = i & 15, n = i >> 4;
        float m = mu[i], s = sigma[i];            // i == n*16+kk, coalesced
        float c = __fdividef(0.5f, s * s);
        float bt = 2.0f * c * m * LOG2E;
        float qt = -c * LOG2E;
        u32 bh = tf32_bits(bt);
        u32 qh = tf32_bits(qt);
        sBl[kk * PL + n] = make_float2(__uint_as_float(bh), bt - __uint_as_float(bh));
        sBl[(kk + 16) * PL + n] = make_float2(__uint_as_float(qh), qt - __uint_as_float(qh));
        sBz[kk * PZ + n] = __uint_as_float(tf32_bits(rho[n * 17 + kk]));
    }
    if (tid < 64) {
        float f = 0.0f;
        for (int a = 0; a < 16; a++) {
            float m = mu[tid * 16 + a], s = sigma[tid * 16 + a];
            f -= m * m * __fdividef(0.5f, s * s);
        }
        sFB[tid] = make_float2(f * LOG2E, rho[tid * 17 + 16]);
    }
    __syncthreads();

    for (int t = 0; t < TILES; t++) {
        const int rowBase = (blockIdx.x + t * GRID) * BLOCK + w * 32;

        // ---- A fragments: rows {g,g+8} of 2 m-tiles; k-cols tig+4e ----
        u32 ah[2][4][4], al[2][4][4];
#pragma unroll
        for (int mt = 0; mt < 2; mt++)
#pragma unroll
            for (int rh = 0; rh < 2; rh++) {
                const float* xr = x + (size_t)(rowBase + mt * 16 + rh * 8 + g) * 16 + tig;
#pragma unroll
                for (int e = 0; e < 4; e++) {
                    float v = xr[4 * e];
                    u32 vh = tf32_bits(v);
                    u32 vl = tf32_bits(v - __uint_as_float(vh));
                    float v2 = v * v;
                    u32 v2h = tf32_bits(v2);
                    u32 v2l = tf32_bits(v2 - __uint_as_float(v2h));
                    int ks = e >> 1;
                    int slot = (e & 1) * 2 + rh;
                    ah[mt][ks][slot] = vh;      al[mt][ks][slot] = vl;
                    ah[mt][2 + ks][slot] = v2h; al[mt][2 + ks][slot] = v2l;
                }
            }

        float num[2][2] = {{0.f, 0.f}, {0.f, 0.f}};
        float den[2][2] = {{0.f, 0.f}, {0.f, 0.f}};

        // ---- 8 rule chunks of 8 rules; 3-way-split accumulators ----
        for (int j = 0; j < 8; j++) {
            float c1[2][4] = {{0.f,0.f,0.f,0.f},{0.f,0.f,0.f,0.f}};  // Ahi*Bhi
            float c2[2][4] = {{0.f,0.f,0.f,0.f},{0.f,0.f,0.f,0.f}};  // Alo*Bhi
            float c3[2][4] = {{0.f,0.f,0.f,0.f},{0.f,0.f,0.f,0.f}};  // Ahi*Blo
            float cz[2][4] = {{0.f,0.f,0.f,0.f},{0.f,0.f,0.f,0.f}};
#pragma unroll
            for (int ks = 0; ks < 4; ks++) {
                float2 Bl0 = sBl[(ks * 8 + tig) * PL + j * 8 + g];
                float2 Bl1 = sBl[(ks * 8 + tig + 4) * PL + j * 8 + g];
                u32 b0h = __float_as_uint(Bl0.x), b1h = __float_as_uint(Bl1.x);
                u32 b0l = __float_as_uint(Bl0.y), b1l = __float_as_uint(Bl1.y);
#pragma unroll
                for (int mt = 0; mt < 2; mt++) {
                    mma8(c1[mt], ah[mt][ks], b0h, b1h);
                    mma8(c2[mt], al[mt][ks], b0h, b1h);
                    mma8(c3[mt], ah[mt][ks], b0l, b1l);
                }
            }
#pragma unroll
            for (int ks = 0; ks < 2; ks++) {          // z: K=16, hi only
                u32 bz0 = __float_as_uint(sBz[(ks * 8 + tig) * PZ + j * 8 + g]);
                u32 bz1 = __float_as_uint(sBz[(ks * 8 + tig + 4) * PZ + j * 8 + g]);
#pragma unroll
                for (int mt = 0; mt < 2; mt++)
                    mma8(cz[mt], ah[mt][ks], bz0, bz1);
            }
            // epilogue for rules 8j+2tig, 8j+2tig+1
            float4 q = *reinterpret_cast<const float4*>(&sFB[8 * j + 2 * tig]);
#pragma unroll
            for (int mt = 0; mt < 2; mt++) {
                float l0 = c1[mt][0] + c2[mt][0] + c3[mt][0];
                float l1 = c1[mt][1] + c2[mt][1] + c3[mt][1];
                float l2 = c1[mt][2] + c2[mt][2] + c3[mt][2];
                float l3 = c1[mt][3] + c2[mt][3] + c3[mt][3];
                float w00 = exp2_fast(l0 + q.x);
                float w01 = exp2_fast(l1 + q.z);
                float w10 = exp2_fast(l2 + q.x);
                float w11 = exp2_fast(l3 + q.z);
                num[mt][0] = fmaf(cz[mt][0] + q.y, w00, num[mt][0]);
                num[mt][0] = fmaf(cz[mt][1] + q.w, w01, num[mt][0]);
                num[mt][1] = fmaf(cz[mt][2] + q.y, w10, num[mt][1]);
                num[mt][1] = fmaf(cz[mt][3] + q.w, w11, num[mt][1]);
                den[mt][0] += w00 + w01;
                den[mt][1] += w10 + w11;
            }
        }

        // ---- reduce across 4 tig lanes; tig==0 writes 4 rows ----
#pragma unroll
        for (int mt = 0; mt < 2; mt++)
#pragma unroll
            for (int rh = 0; rh < 2; rh++) {
                float n = num[mt][rh], d = den[mt][rh];
                n += __shfl_xor_sync(0xffffffffu, n, 1);
                d += __shfl_xor_sync(0xffffffffu, d, 1);
                n += __shfl_xor_sync(0xffffffffu, n, 2);
                d += __shfl_xor_sync(0xffffffffu, d, 2);
                if (tig == 0)
                    out[rowBase + mt * 16 + rh * 8 + g] = n / (d + 1e-13f);
            }
    }
}

extern "C" void kernel_launch(void* const* d_in, const int* in_sizes, int n_in,
                              void* d_out, int out_size) {
    const float* x = (const float*)d_in[0];      // [N, 16]
    const float* mu = (const float*)d_in[1];     // [64, 16]
    const float* sigma = (const float*)d_in[2];  // [64, 16]
    const float* rho = (const float*)d_in[3];    // [64, 17]
    float* out = (float*)d_out;                  // [N]

    fuzzy_mma_kernel<<<GRID, BLOCK>>>(x, mu, sigma, rho, out);
}